// round 1
// baseline (speedup 1.0000x reference)
#include <cuda_runtime.h>
#include <math.h>

#define TPB 256
#define MAX_PARTIALS 2048

__device__ float g_partials[MAX_PARTIALS];

__device__ __forceinline__ void box_corners(float x, float y, float w, float l,
                                            float im, float re,
                                            float* cx, float* cy) {
    float yaw = atan2f(im, re);
    float s, c;
    sincosf(yaw, &s, &c);
    float hw = 0.5f * w, hl = 0.5f * l;
    cx[0] = x - hw * c - hl * s;  cy[0] = y - hw * s + hl * c;
    cx[1] = x - hw * c + hl * s;  cy[1] = y - hw * s - hl * c;
    cx[2] = x + hw * c + hl * s;  cy[2] = y + hw * s - hl * c;
    cx[3] = x + hw * c - hl * s;  cy[3] = y + hw * s + hl * c;
}

__global__ void giou_kernel(const float* __restrict__ pred,
                            const float* __restrict__ tgt,
                            float* __restrict__ out, int n) {
    int i = blockIdx.x * TPB + threadIdx.x;
    float giou = 0.0f;

    if (i < n) {
        const float* pb = pred + 6 * i;
        const float* tb = tgt + 6 * i;
        float pX = pb[0], pY = pb[1], pW = pb[2], pL = pb[3], pIm = pb[4], pRe = pb[5];
        float tX = tb[0], tY = tb[1], tW = tb[2], tL = tb[3], tIm = tb[4], tRe = tb[5];

        float pcx[4], pcy[4], tcx[4], tcy[4];
        box_corners(pX, pY, pW, pL, pIm, pRe, pcx, pcy);
        box_corners(tX, tY, tW, tL, tIm, tRe, tcx, tcy);

        // ---- Sutherland-Hodgman clip: pred quad clipped by target quad ----
        // Replicates reference semantics exactly, including the "frozen"
        // behavior: if a clip pass empties the polygon, keep the PRE-clip
        // polygon and stop clipping (reference bug, must match).
        float px[8], py[8];
        int np = 4;
        #pragma unroll
        for (int k = 0; k < 4; k++) { px[k] = pcx[k]; py[k] = pcy[k]; }
        bool frozen = false;

        for (int e = 0; e < 4; e++) {
            if (frozen || np <= 2) continue;
            int e1 = (e + 1) & 3;
            float Px = tcx[e], Py = tcy[e];
            float Qx = tcx[e1], Qy = tcy[e1];
            float a = Qy - Py;
            float b = Px - Qx;
            float c = Qx * Py - Qy * Px;

            float vals[8];
            for (int j = 0; j < np; j++)
                vals[j] = a * px[j] + b * py[j] + c;

            float nx[8], ny[8];
            int nn = 0;
            for (int j = 0; j < np; j++) {
                int jn = (j + 1 == np) ? 0 : j + 1;
                float v = vals[j], tv = vals[jn];
                if (v <= 0.0f) {                  // keep: inside (vals <= 0)
                    nx[nn] = px[j];
                    ny[nn] = py[j];
                    nn++;
                }
                if (v * tv < 0.0f) {              // crossing: strict sign change
                    float a2 = py[jn] - py[j];
                    float b2 = px[j] - px[jn];
                    float c2 = px[jn] * py[j] - py[jn] * px[j];
                    float wd = a * b2 - b * a2;
                    nx[nn] = (b * c2 - c * b2) / wd;
                    ny[nn] = (c * a2 - a * c2) / wd;
                    nn++;
                }
            }
            if (nn > 0) {
                np = nn;
                for (int j = 0; j < nn; j++) { px[j] = nx[j]; py[j] = ny[j]; }
            } else {
                frozen = true;                    // keep old polygon, stop
            }
        }

        // ---- shoelace area of clipped polygon ----
        float inter = 0.0f;
        if (np > 2) {
            float s2 = 0.0f;
            for (int j = 0; j < np; j++) {
                int jn = (j + 1 == np) ? 0 : j + 1;
                s2 += px[j] * py[jn] - py[j] * px[jn];
            }
            inter = 0.5f * fabsf(s2);
        }

        float pa = pW * pL;
        float ta = tW * tL;
        float uni = pa + ta - inter;
        float iou = inter / (uni + 1e-16f);

        // ---- convex hull area of 8 combined corners ----
        // Replicates the reference's all-pairs formulation, incl. epsilons.
        float hx[8], hy[8];
        #pragma unroll
        for (int k = 0; k < 4; k++) {
            hx[k] = pcx[k];     hy[k] = pcy[k];
            hx[4 + k] = tcx[k]; hy[4 + k] = tcy[k];
        }
        float hs = 0.0f;
        for (int ii = 0; ii < 8; ii++) {
            float xi = hx[ii], yi = hy[ii];
            for (int jj = 0; jj < 8; jj++) {
                float ex = hx[jj] - xi;
                float ey = hy[jj] - yi;
                if (ex * ex + ey * ey <= 1e-12f) continue;
                bool left = true;
                #pragma unroll
                for (int kk = 0; kk < 8; kk++) {
                    float cr = ex * (hy[kk] - yi) - ey * (hx[kk] - xi);
                    if (cr < -1e-6f) { left = false; break; }
                }
                if (left) hs += xi * hy[jj] - yi * hx[jj];
            }
        }
        float hull = 0.5f * fabsf(hs);

        out[i] = iou;
        giou = 1.0f - (iou - (hull - uni) / (hull + 1e-16f));
    }

    // ---- deterministic block reduction of giou ----
    __shared__ float sh[TPB];
    sh[threadIdx.x] = giou;
    __syncthreads();
    #pragma unroll
    for (int s = TPB / 2; s > 0; s >>= 1) {
        if (threadIdx.x < s) sh[threadIdx.x] += sh[threadIdx.x + s];
        __syncthreads();
    }
    if (threadIdx.x == 0) g_partials[blockIdx.x] = sh[0];
}

__global__ void reduce_kernel(float* __restrict__ out, int nblocks, int n) {
    __shared__ float sh[1024];
    int t = threadIdx.x;
    float v = 0.0f;
    for (int j = t; j < nblocks; j += 1024) v += g_partials[j];
    sh[t] = v;
    __syncthreads();
    #pragma unroll
    for (int s = 512; s > 0; s >>= 1) {
        if (t < s) sh[t] += sh[t + s];
        __syncthreads();
    }
    if (t == 0) out[n] = sh[0];
}

extern "C" void kernel_launch(void* const* d_in, const int* in_sizes, int n_in,
                              void* d_out, int out_size) {
    const float* pred = (const float*)d_in[0];
    const float* tgt  = (const float*)d_in[1];
    float* out = (float*)d_out;
    int n = in_sizes[0] / 6;
    int nblocks = (n + TPB - 1) / TPB;
    giou_kernel<<<nblocks, TPB>>>(pred, tgt, out, n);
    reduce_kernel<<<1, 1024>>>(out, nblocks, n);
}

// round 2
// speedup vs baseline: 1.6708x; 1.6708x over previous
#include <cuda_runtime.h>
#include <math.h>

#define TPB 256

__device__ float g_partials[1024];
__device__ unsigned int g_count;

__device__ __forceinline__ void box_corners(float x, float y, float w, float l,
                                            float im, float re,
                                            float* cx, float* cy) {
    // cos(atan2(im,re)) = re/r, sin(atan2(im,re)) = im/r
    float rinv = rsqrtf(fmaf(im, im, re * re));
    float c = re * rinv;
    float s = im * rinv;
    float hw = 0.5f * w, hl = 0.5f * l;
    cx[0] = x - hw * c - hl * s;  cy[0] = y - hw * s + hl * c;
    cx[1] = x - hw * c + hl * s;  cy[1] = y - hw * s - hl * c;
    cx[2] = x + hw * c + hl * s;  cy[2] = y + hw * s - hl * c;
    cx[3] = x + hw * c - hl * s;  cy[3] = y + hw * s + hl * c;
}

// One Sutherland-Hodgman clip pass against half-plane (a,b,c), fully
// registerized: all array indices are compile-time constants after unroll.
// INCAP/OUTCAP are geometric vertex-count bounds (4+e / 5+e for edge e).
// Replicates reference semantics: keep = (val <= 0), crossing = strict sign
// change, and the "frozen" behavior (empty result -> keep pre-clip polygon).
template <int INCAP, int OUTCAP>
__device__ __forceinline__ void clip_edge(float a, float b, float c,
                                          float (&ax)[8], float (&ay)[8],
                                          int& np, bool& frozen) {
    if (frozen || np <= 2) return;

    float v[8];
#pragma unroll
    for (int j = 0; j < INCAP; j++)
        v[j] = a * ax[j] + b * ay[j] + c;

    float bx[8], by[8];
#pragma unroll
    for (int s = 0; s < OUTCAP; s++) { bx[s] = 0.0f; by[s] = 0.0f; }

    int nn = 0;
#pragma unroll
    for (int j = 0; j < INCAP; j++) {
        bool act  = (j < np);
        bool last = (j + 1 == np);
        const int j1 = (j + 1 < INCAP) ? (j + 1) : 0;
        float tv = last ? v[0]  : v[j1];
        float tx = last ? ax[0] : ax[j1];
        float ty = last ? ay[0] : ay[j1];

        bool keep = act && (v[j] <= 0.0f);
        bool crs  = act && (v[j] * tv < 0.0f);

#pragma unroll
        for (int s = 0; s < OUTCAP; s++) {
            bool w = keep && (nn == s);
            bx[s] = w ? ax[j] : bx[s];
            by[s] = w ? ay[j] : by[s];
        }
        nn += keep ? 1 : 0;

        float a2 = ty - ay[j];
        float b2 = ax[j] - tx;
        float c2 = tx * ay[j] - ty * ax[j];
        float wd = a * b2 - b * a2;
        float iw = __fdividef(1.0f, wd);
        float ix = (b * c2 - c * b2) * iw;
        float iy = (c * a2 - a * c2) * iw;

#pragma unroll
        for (int s = 0; s < OUTCAP; s++) {
            bool w = crs && (nn == s);
            bx[s] = w ? ix : bx[s];
            by[s] = w ? iy : by[s];
        }
        nn += crs ? 1 : 0;
    }

    if (nn > 0) {
        np = (nn < OUTCAP) ? nn : OUTCAP;
#pragma unroll
        for (int s = 0; s < OUTCAP; s++) { ax[s] = bx[s]; ay[s] = by[s]; }
    } else {
        frozen = true;  // keep old polygon (reference semantics)
    }
}

__global__ void __launch_bounds__(TPB)
giou_kernel(const float* __restrict__ pred,
            const float* __restrict__ tgt,
            float* __restrict__ out, int n) {
    int i = blockIdx.x * TPB + threadIdx.x;
    float giou = 0.0f;

    if (i < n) {
        const float* pb = pred + 6 * i;
        const float* tb = tgt + 6 * i;
        float pX = __ldg(pb + 0), pY = __ldg(pb + 1), pW = __ldg(pb + 2);
        float pL = __ldg(pb + 3), pIm = __ldg(pb + 4), pRe = __ldg(pb + 5);
        float tX = __ldg(tb + 0), tY = __ldg(tb + 1), tW = __ldg(tb + 2);
        float tL = __ldg(tb + 3), tIm = __ldg(tb + 4), tRe = __ldg(tb + 5);

        float pcx[4], pcy[4], tcx[4], tcy[4];
        box_corners(pX, pY, pW, pL, pIm, pRe, pcx, pcy);
        box_corners(tX, tY, tW, tL, tIm, tRe, tcx, tcy);

        // ---- clip pred quad by target quad (4 half-planes) ----
        float ax[8], ay[8];
#pragma unroll
        for (int k = 0; k < 4; k++) { ax[k] = pcx[k]; ay[k] = pcy[k]; }
#pragma unroll
        for (int k = 4; k < 8; k++) { ax[k] = pcx[0]; ay[k] = pcy[0]; }
        int np = 4;
        bool frozen = false;

        {
            float a0 = tcy[1] - tcy[0], b0 = tcx[0] - tcx[1];
            float c0 = tcx[1] * tcy[0] - tcy[1] * tcx[0];
            clip_edge<4, 5>(a0, b0, c0, ax, ay, np, frozen);
            float a1 = tcy[2] - tcy[1], b1 = tcx[1] - tcx[2];
            float c1 = tcx[2] * tcy[1] - tcy[2] * tcx[1];
            clip_edge<5, 6>(a1, b1, c1, ax, ay, np, frozen);
            float a2 = tcy[3] - tcy[2], b2 = tcx[2] - tcx[3];
            float c2 = tcx[3] * tcy[2] - tcy[3] * tcx[2];
            clip_edge<6, 7>(a2, b2, c2, ax, ay, np, frozen);
            float a3 = tcy[0] - tcy[3], b3 = tcx[3] - tcx[0];
            float c3 = tcx[0] * tcy[3] - tcy[0] * tcx[3];
            clip_edge<7, 8>(a3, b3, c3, ax, ay, np, frozen);
        }

        // ---- shoelace of clipped polygon ----
        float s2 = 0.0f;
#pragma unroll
        for (int j = 0; j < 8; j++) {
            bool act = (j < np);
            bool last = (j + 1 == np);
            const int j1 = (j + 1) & 7;
            float nx = last ? ax[0] : ax[j1];
            float ny = last ? ay[0] : ay[j1];
            float t = ax[j] * ny - ay[j] * nx;
            s2 += act ? t : 0.0f;
        }
        float inter = (np > 2) ? 0.5f * fabsf(s2) : 0.0f;

        float pa = pW * pL;
        float ta = tW * tL;
        float uni = pa + ta - inter;
        float iou = inter / (uni + 1e-16f);

        // ---- convex hull area of the 8 combined corners (branchless) ----
        float hx[8], hy[8];
#pragma unroll
        for (int k = 0; k < 4; k++) {
            hx[k] = pcx[k];     hy[k] = pcy[k];
            hx[4 + k] = tcx[k]; hy[4 + k] = tcy[k];
        }
        float hs = 0.0f;
#pragma unroll
        for (int ii = 0; ii < 8; ii++) {
            float xi = hx[ii], yi = hy[ii];
            float dx[8], dy[8];
#pragma unroll
            for (int k = 0; k < 8; k++) { dx[k] = hx[k] - xi; dy[k] = hy[k] - yi; }
#pragma unroll
            for (int jj = 0; jj < 8; jj++) {
                if (jj == ii) continue;
                float ex = dx[jj], ey = dy[jj];
                float mn = 0.0f;  // cr at k==ii and k==jj is exactly 0
#pragma unroll
                for (int k = 0; k < 8; k++) {
                    if (k == ii || k == jj) continue;
                    float cr = ex * dy[k] - ey * dx[k];
                    mn = fminf(mn, cr);
                }
                float len2 = ex * ex + ey * ey;
                bool valid = (mn >= -1e-6f) && (len2 > 1e-12f);
                float contrib = xi * hy[jj] - yi * hx[jj];
                hs += valid ? contrib : 0.0f;
            }
        }
        float hull = 0.5f * fabsf(hs);

        out[i] = iou;
        giou = 1.0f - (iou - (hull - uni) / (hull + 1e-16f));
    }

    // ---- in-kernel deterministic reduction (no second launch) ----
#pragma unroll
    for (int off = 16; off > 0; off >>= 1)
        giou += __shfl_down_sync(0xffffffffu, giou, off);

    __shared__ float wsum[TPB / 32];
    __shared__ bool isLast;
    if ((threadIdx.x & 31) == 0) wsum[threadIdx.x >> 5] = giou;
    __syncthreads();

    if (threadIdx.x == 0) {
        float bs = 0.0f;
#pragma unroll
        for (int w = 0; w < TPB / 32; w++) bs += wsum[w];
        g_partials[blockIdx.x] = bs;
        __threadfence();
        unsigned c = atomicAdd(&g_count, 1u);
        isLast = (c == gridDim.x - 1);
    }
    __syncthreads();

    if (isLast) {
        __threadfence();
        int t = threadIdx.x;
        float v = 0.0f;
        for (int j = t; j < (int)gridDim.x; j += TPB)
            v += ((volatile float*)g_partials)[j];
#pragma unroll
        for (int off = 16; off > 0; off >>= 1)
            v += __shfl_down_sync(0xffffffffu, v, off);
        if ((t & 31) == 0) wsum[t >> 5] = v;
        __syncthreads();
        if (t == 0) {
            float tot = 0.0f;
#pragma unroll
            for (int w = 0; w < TPB / 32; w++) tot += wsum[w];
            out[n] = tot;
            g_count = 0;  // reset for next graph replay
        }
    }
}

extern "C" void kernel_launch(void* const* d_in, const int* in_sizes, int n_in,
                              void* d_out, int out_size) {
    const float* pred = (const float*)d_in[0];
    const float* tgt  = (const float*)d_in[1];
    float* out = (float*)d_out;
    int n = in_sizes[0] / 6;
    int nblocks = (n + TPB - 1) / TPB;
    giou_kernel<<<nblocks, TPB>>>(pred, tgt, out, n);
}